// round 5
// baseline (speedup 1.0000x reference)
#include <cuda_runtime.h>
#include <cuda_bf16.h>
#include <cstdint>
#include <cstddef>

#define NHEAD 8
#define HID 512
#define DK 64
#define SEQ 1024
#define BATCH 4
#define TOK 4096
#define WIN 34
#define KDIM 512

#define BK 32
#define A_TILE_B 16384                 // 256 rows * 64B
#define B_TILE_B 8192                  // 128 rows * 64B
#define STAGE_B 49152                  // Ahi|Alo|Bhi|Blo
#define OFF_ALO 16384
#define OFF_BHI 32768
#define OFF_BLO 40960
#define GSMEM (3 * STAGE_B)            // 147456

// ---------------- scratch ----------------
__device__ float g_st  [2ull * TOK * HID];
__device__ float g_qkv [2ull * TOK * 3 * HID];
__device__ float g_y   [2ull * TOK * HID];
__device__ __nv_bfloat16 g_act_hi [2ull * TOK * HID];
__device__ __nv_bfloat16 g_act_lo [2ull * TOK * HID];
__device__ __nv_bfloat16 g_attn_hi[2ull * TOK * HID];
__device__ __nv_bfloat16 g_attn_lo[2ull * TOK * HID];
__device__ __nv_bfloat16 g_yhi    [2ull * TOK * HID];
__device__ __nv_bfloat16 g_ylo    [2ull * TOK * HID];
__device__ __nv_bfloat16 g_y2hi   [2ull * TOK * HID];
__device__ __nv_bfloat16 g_y2lo   [2ull * TOK * HID];
__device__ __nv_bfloat16 g_wqkv_hi[4194304];
__device__ __nv_bfloat16 g_wqkv_lo[4194304];
__device__ __nv_bfloat16 g_whw_hi [4194304];
__device__ __nv_bfloat16 g_whw_lo [4194304];

// ---------------- helpers ----------------
__device__ __forceinline__ uint32_t s2u(const void* p) {
    uint32_t a;
    asm("{ .reg .u64 t; cvta.to.shared.u64 t, %1; cvt.u32.u64 %0, t; }" : "=r"(a) : "l"(p));
    return a;
}
__device__ __forceinline__ void cpasync16(uint32_t dst, const void* src) {
    asm volatile("cp.async.cg.shared.global [%0], [%1], 16;" :: "r"(dst), "l"(src));
}
__device__ __forceinline__ void ldmx4(uint32_t* d, uint32_t a) {
    asm volatile("ldmatrix.sync.aligned.m8n8.x4.shared.b16 {%0,%1,%2,%3}, [%4];"
        : "=r"(d[0]), "=r"(d[1]), "=r"(d[2]), "=r"(d[3]) : "r"(a));
}
__device__ __forceinline__ void mma16816(float* c, const uint32_t* a, const uint32_t* b) {
    asm volatile("mma.sync.aligned.m16n8k16.row.col.f32.bf16.bf16.f32 "
        "{%0,%1,%2,%3}, {%4,%5,%6,%7}, {%8,%9}, {%0,%1,%2,%3};"
        : "+f"(c[0]), "+f"(c[1]), "+f"(c[2]), "+f"(c[3])
        : "r"(a[0]), "r"(a[1]), "r"(a[2]), "r"(a[3]), "r"(b[0]), "r"(b[1]));
}
__device__ __forceinline__ uint32_t pack_bf2(float x, float y) {
    __nv_bfloat162 t = __floats2bfloat162_rn(x, y);
    return *(uint32_t*)&t;
}
__device__ __forceinline__ void split1(float v, float& hi, float& lo) {
    __nv_bfloat16 h = __float2bfloat16(v);
    hi = __bfloat162float(h);
    lo = v - hi;
}

// ---------------- weight conversions ----------------
__global__ void conv_split(const float* __restrict__ src,
                           __nv_bfloat16* __restrict__ hi,
                           __nv_bfloat16* __restrict__ lo)
{
    const size_t i = (size_t)blockIdx.x * blockDim.x + threadIdx.x;
    float4 v = ((const float4*)src)[i];
    float f[4] = {v.x, v.y, v.z, v.w};
    __nv_bfloat16 h[4], l[4];
#pragma unroll
    for (int k = 0; k < 4; k++) {
        h[k] = __float2bfloat16(f[k]);
        l[k] = __float2bfloat16(f[k] - __bfloat162float(h[k]));
    }
    *(uint2*)(hi + 4 * i) = *(uint2*)h;
    *(uint2*)(lo + 4 * i) = *(uint2*)l;
}

// highway weights: interleave rows so out col 2j=nonlin_j, 2j+1=gate_j
__global__ void conv_hw(const float* __restrict__ src,
                        __nv_bfloat16* __restrict__ hi,
                        __nv_bfloat16* __restrict__ lo)
{
    const size_t idx = (size_t)blockIdx.x * blockDim.x + threadIdx.x;
    const size_t m   = idx >> 17;
    const size_t rem = idx & 131071;
    const int    r   = (int)(rem >> 7);
    const size_t c4  = rem & 127;
    const int dr = (r < 512) ? (2 * r) : (2 * (r - 512) + 1);
    float4 v = ((const float4*)src)[idx];
    float f[4] = {v.x, v.y, v.z, v.w};
    __nv_bfloat16 h[4], l[4];
#pragma unroll
    for (int k = 0; k < 4; k++) {
        h[k] = __float2bfloat16(f[k]);
        l[k] = __float2bfloat16(f[k] - __bfloat162float(h[k]));
    }
    const size_t dst = (m << 17) + (size_t)dr * 128 + c4;
    *(uint2*)(hi + 4 * dst) = *(uint2*)h;
    *(uint2*)(lo + 4 * dst) = *(uint2*)l;
}

// ---------------- fused HMMA GEMM ----------------
// CTA tile 256(M) x 128(N), 512 threads, warp tile 64x32 (4x4 warps), BK=32.
// C[M,N] = A[M,512] @ B[N,512]^T + bias  (split-bf16 3-pass)
// mode 0: write C fp32
// mode 1: write C fp32 + bf16 split to Shi/Slo
// mode 2: highway mid: y' = sig(g)*y + (1-sig)*relu(n); write Yv + split
// mode 3: highway final: v = y' (+ St); St=v, Out=v, split
__global__ __launch_bounds__(512, 1)
void gemm_fused(const __nv_bfloat16* __restrict__ Ahi, const __nv_bfloat16* __restrict__ Alo,
                const __nv_bfloat16* __restrict__ Bhi, const __nv_bfloat16* __restrict__ Blo,
                const float* __restrict__ bias, float* __restrict__ C,
                __nv_bfloat16* __restrict__ Shi, __nv_bfloat16* __restrict__ Slo,
                float* __restrict__ Yv, float* __restrict__ St, float* __restrict__ Out,
                int N, size_t sB, size_t sbias, size_t sC, int mode, int add_res)
{
    extern __shared__ char smem[];
    const uint32_t sbase = s2u(smem);
    const int tid = threadIdx.x, lane = tid & 31, wid = tid >> 5;
    const int wm = wid & 3, wn = wid >> 2;
    const int dir = blockIdx.z;
    const int bm = blockIdx.y * 256, bn = blockIdx.x * 128;
    Ahi += (size_t)dir * TOK * KDIM; Alo += (size_t)dir * TOK * KDIM;
    Bhi += (size_t)dir * sB;         Blo += (size_t)dir * sB;
    bias += (size_t)dir * sbias;

    // cp.async coords: A 256 rows, 2 chunks/thread; B 128 rows, 1 chunk/thread
    const int rA  = tid >> 1;
    const int cA0 = (tid & 1) * 2;
    const uint32_t xA = (uint32_t)((rA >> 1) & 3);
    const uint32_t sroA0 = (uint32_t)rA * 64 + (((uint32_t)cA0 ^ xA) << 4);
    const uint32_t sroA1 = (uint32_t)rA * 64 + ((((uint32_t)cA0 + 1) ^ xA) << 4);
    const int rB = tid >> 2;
    const int cB = tid & 3;
    const uint32_t sroB = (uint32_t)rB * 64 + (((uint32_t)cB ^ (uint32_t)((rB >> 1) & 3)) << 4);

    // ldmatrix coords
    const int m8 = lane >> 3, l7 = lane & 7;
    const uint32_t xm = (uint32_t)((l7 >> 1) & 3);
    const uint32_t a_base = (uint32_t)(wm * 64 + (m8 & 1) * 8 + l7) * 64;
    const uint32_t b_base = (uint32_t)(wn * 32 + (m8 >> 1) * 8 + l7) * 64;
    const uint32_t a_c = (((uint32_t)(m8 >> 1)) ^ (xm & 1)) << 4;
    const uint32_t b_c = (((uint32_t)(m8 & 1)) ^ (xm & 1)) << 4;
    const uint32_t kof[2] = { (xm & 2) << 4, (2u ^ (xm & 2)) << 4 };

    float acc[4][4][4];
#pragma unroll
    for (int i = 0; i < 4; i++)
#pragma unroll
        for (int j = 0; j < 4; j++)
#pragma unroll
            for (int k = 0; k < 4; k++) acc[i][j][k] = 0.f;

#define LOAD_CHUNK(ch, stg) do {                                                   \
        const uint32_t _sb = sbase + (uint32_t)(stg) * STAGE_B;                    \
        const int _ke = (ch) * BK;                                                 \
        const size_t _ga = (size_t)(bm + rA) * KDIM + _ke + cA0 * 8;               \
        cpasync16(_sb + sroA0,           Ahi + _ga);                               \
        cpasync16(_sb + sroA1,           Ahi + _ga + 8);                           \
        cpasync16(_sb + OFF_ALO + sroA0, Alo + _ga);                               \
        cpasync16(_sb + OFF_ALO + sroA1, Alo + _ga + 8);                           \
        const size_t _gb = (size_t)(bn + rB) * KDIM + _ke + cB * 8;                \
        cpasync16(_sb + OFF_BHI + sroB,  Bhi + _gb);                               \
        cpasync16(_sb + OFF_BLO + sroB,  Blo + _gb);                               \
        asm volatile("cp.async.commit_group;" ::: "memory");                       \
    } while (0)

    LOAD_CHUNK(0, 0);
    LOAD_CHUNK(1, 1);

    int stg_c = 0;
    int stg_l = 2;
#pragma unroll 1
    for (int ch = 0; ch < 16; ch++) {
        if (ch < 15) asm volatile("cp.async.wait_group 1;" ::: "memory");
        else         asm volatile("cp.async.wait_group 0;" ::: "memory");
        __syncthreads();
        if (ch + 2 < 16) LOAD_CHUNK(ch + 2, stg_l);

        const uint32_t sb = sbase + (uint32_t)stg_c * STAGE_B;
#pragma unroll
        for (int kk = 0; kk < 2; kk++) {
            uint32_t ah[4][4], al[4][4], bh[2][4], bl[2][4];
#pragma unroll
            for (int nj = 0; nj < 2; nj++) {
                const uint32_t ba = sb + OFF_BHI + b_base + nj * 1024 + b_c + kof[kk];
                ldmx4(bh[nj], ba);
                ldmx4(bl[nj], ba + (OFF_BLO - OFF_BHI));
            }
#pragma unroll
            for (int mi = 0; mi < 4; mi++) {
                const uint32_t aa = sb + a_base + mi * 1024 + a_c + kof[kk];
                ldmx4(ah[mi], aa);
                ldmx4(al[mi], aa + OFF_ALO);
            }
#pragma unroll
            for (int mi = 0; mi < 4; mi++)
#pragma unroll
                for (int ni = 0; ni < 4; ni++) {
                    const uint32_t* fh = &bh[ni >> 1][(ni & 1) * 2];
                    const uint32_t* fl = &bl[ni >> 1][(ni & 1) * 2];
                    mma16816(acc[mi][ni], ah[mi], fh);
                    mma16816(acc[mi][ni], ah[mi], fl);
                    mma16816(acc[mi][ni], al[mi], fh);
                }
        }
        stg_c = (stg_c == 2) ? 0 : stg_c + 1;
        stg_l = (stg_l == 2) ? 0 : stg_l + 1;
    }
#undef LOAD_CHUNK

    // ---------------- epilogue ----------------
    const int gr = lane >> 2, gc = (lane & 3) * 2;

    if (mode <= 1) {
        float* Cp = C + (size_t)dir * sC;
        __nv_bfloat16* SH = Shi ? (Shi + (size_t)dir * sC) : nullptr;
        __nv_bfloat16* SL = Slo ? (Slo + (size_t)dir * sC) : nullptr;
#pragma unroll
        for (int mi = 0; mi < 4; mi++) {
#pragma unroll
            for (int ni = 0; ni < 4; ni++) {
                const int row0 = bm + wm * 64 + mi * 16 + gr;
                const int col  = bn + wn * 32 + ni * 8 + gc;
                const float b0 = bias[col], b1 = bias[col + 1];
                const float v00 = acc[mi][ni][0] + b0, v01 = acc[mi][ni][1] + b1;
                const float v10 = acc[mi][ni][2] + b0, v11 = acc[mi][ni][3] + b1;
                *(float2*)&Cp[(size_t)row0 * N + col]       = make_float2(v00, v01);
                *(float2*)&Cp[(size_t)(row0 + 8) * N + col] = make_float2(v10, v11);
                if (mode == 1) {
                    float h0, l0, h1, l1;
                    split1(v00, h0, l0); split1(v01, h1, l1);
                    *(uint32_t*)&SH[(size_t)row0 * N + col] = pack_bf2(h0, h1);
                    *(uint32_t*)&SL[(size_t)row0 * N + col] = pack_bf2(l0, l1);
                    split1(v10, h0, l0); split1(v11, h1, l1);
                    *(uint32_t*)&SH[(size_t)(row0 + 8) * N + col] = pack_bf2(h0, h1);
                    *(uint32_t*)&SL[(size_t)(row0 + 8) * N + col] = pack_bf2(l0, l1);
                }
            }
        }
    } else {
        float* Y = Yv + (size_t)dir * TOK * HID;
        float* S = St + (size_t)dir * TOK * HID;
        __nv_bfloat16* SH = Shi + (size_t)dir * TOK * HID;
        __nv_bfloat16* SL = Slo + (size_t)dir * TOK * HID;
#pragma unroll
        for (int mi = 0; mi < 4; mi++) {
#pragma unroll
            for (int ni = 0; ni < 4; ni++) {
                const int row0 = bm + wm * 64 + mi * 16 + gr;
                const int col  = bn + wn * 32 + ni * 8 + gc;
                const int j    = col >> 1;
                const float bnl = bias[j], bgt = bias[j + HID];
#pragma unroll
                for (int rr = 0; rr < 2; rr++) {
                    const int row = row0 + rr * 8;
                    const float n = acc[mi][ni][rr * 2]     + bnl;
                    const float g = acc[mi][ni][rr * 2 + 1] + bgt;
                    const size_t o = (size_t)row * HID + j;
                    const float yo = Y[o];
                    const float s = 1.f / (1.f + __expf(-g));
                    float v = s * yo + (1.f - s) * fmaxf(n, 0.f);
                    if (mode == 2) {
                        Y[o] = v;
                    } else {
                        if (add_res) v += S[o];
                        S[o] = v;
                        Out[(size_t)row * (2 * HID) + (size_t)dir * HID + j] = v;
                    }
                    float h, l;
                    split1(v, h, l);
                    SH[o] = __float2bfloat16(h);
                    SL[o] = __float2bfloat16(l);
                }
            }
        }
    }
}

// ---------------- banded local attention ----------------
__global__ void attn_kernel(const float* __restrict__ rel_l)
{
    const int dir = blockIdx.z;
    const int bh = blockIdx.y;
    const int b = bh >> 3;
    const int h = bh & 7;
    const int w = threadIdx.x >> 5;
    const int lane = threadIdx.x & 31;
    const int i = blockIdx.x * 8 + w;

    __shared__ float sbias[WIN];
    if (threadIdx.x < WIN)
        sbias[threadIdx.x] = rel_l[((size_t)dir * NHEAD + h) * WIN + threadIdx.x];
    __syncthreads();

    const size_t dbase = (size_t)dir * TOK * (3 * HID);
    const int tb = b * SEQ;
    const float2 qv = *(const float2*)(g_qkv + dbase + (size_t)(tb + i) * (3 * HID) + h * DK + 2 * lane);

    float m = -1e30f, den = 0.f;
    float2 acc = make_float2(0.f, 0.f);

#pragma unroll 1
    for (int jj = 0; jj < WIN; jj++) {
        const int j = (dir == 0) ? (i - (WIN - 1) + jj) : (i + jj);
        if (j < 0 || j >= SEQ) continue;
        const size_t kbase = dbase + (size_t)(tb + j) * (3 * HID) + h * DK + 2 * lane;
        const float2 kv = *(const float2*)(g_qkv + kbase + HID);
        float p = qv.x * kv.x + qv.y * kv.y;
#pragma unroll
        for (int o = 16; o > 0; o >>= 1) p += __shfl_xor_sync(0xffffffffu, p, o);
        const float s = p * 0.125f + sbias[jj];
        const float mnew = fmaxf(m, s);
        const float sc = __expf(m - mnew);
        const float e  = __expf(s - mnew);
        const float2 vv = *(const float2*)(g_qkv + kbase + 2 * HID);
        den   = den   * sc + e;
        acc.x = acc.x * sc + e * vv.x;
        acc.y = acc.y * sc + e * vv.y;
        m = mnew;
    }
    const float inv = 1.0f / den;
    const float ox = acc.x * inv, oy = acc.y * inv;
    float h0, l0, h1, l1;
    split1(ox, h0, l0); split1(oy, h1, l1);
    const size_t oidx = (size_t)dir * TOK * HID + (size_t)(tb + i) * HID + h * DK + 2 * lane;
    *(uint32_t*)&g_attn_hi[oidx] = pack_bf2(h0, h1);
    *(uint32_t*)&g_attn_lo[oidx] = pack_bf2(l0, l1);
}

// ---------------- init ----------------
__global__ void init_state(const float* __restrict__ in)
{
    const size_t idx = (size_t)blockIdx.x * blockDim.x + threadIdx.x;
    const float4 v = *(const float4*)(in + idx * 4);
    float h[4], l[4];
    split1(v.x, h[0], l[0]); split1(v.y, h[1], l[1]);
    split1(v.z, h[2], l[2]); split1(v.w, h[3], l[3]);
    const uint2 ph = make_uint2(pack_bf2(h[0], h[1]), pack_bf2(h[2], h[3]));
    const uint2 pl = make_uint2(pack_bf2(l[0], l[1]), pack_bf2(l[2], l[3]));
    *(uint2*)&g_act_hi[idx * 4] = ph;
    *(uint2*)&g_act_lo[idx * 4] = pl;
    *(uint2*)&g_act_hi[(size_t)TOK * HID + idx * 4] = ph;
    *(uint2*)&g_act_lo[(size_t)TOK * HID + idx * 4] = pl;
}

// ---------------- launch ----------------
extern "C" void kernel_launch(void* const* d_in, const int* in_sizes, int n_in,
                              void* d_out, int out_size)
{
    const float* inputs = (const float*)d_in[0];
    const float* qkv_w  = (const float*)d_in[2];
    const float* qkv_b  = (const float*)d_in[3];
    const float* rel    = (const float*)d_in[4];
    const float* hw_w   = (const float*)d_in[5];
    const float* hw_b   = (const float*)d_in[6];
    float* out = (float*)d_out;

    float *qkvp, *yv, *st;
    __nv_bfloat16 *ahi, *alo, *athi, *atlo, *yhi, *ylo, *y2hi, *y2lo, *wqh, *wql, *whh, *whl;
    cudaGetSymbolAddress((void**)&qkvp, g_qkv);
    cudaGetSymbolAddress((void**)&yv,   g_y);
    cudaGetSymbolAddress((void**)&st,   g_st);
    cudaGetSymbolAddress((void**)&ahi,  g_act_hi);
    cudaGetSymbolAddress((void**)&alo,  g_act_lo);
    cudaGetSymbolAddress((void**)&athi, g_attn_hi);
    cudaGetSymbolAddress((void**)&atlo, g_attn_lo);
    cudaGetSymbolAddress((void**)&yhi,  g_yhi);
    cudaGetSymbolAddress((void**)&ylo,  g_ylo);
    cudaGetSymbolAddress((void**)&y2hi, g_y2hi);
    cudaGetSymbolAddress((void**)&y2lo, g_y2lo);
    cudaGetSymbolAddress((void**)&wqh,  g_wqkv_hi);
    cudaGetSymbolAddress((void**)&wql,  g_wqkv_lo);
    cudaGetSymbolAddress((void**)&whh,  g_whw_hi);
    cudaGetSymbolAddress((void**)&whl,  g_whw_lo);

    cudaFuncSetAttribute(gemm_fused, cudaFuncAttributeMaxDynamicSharedMemorySize, GSMEM);

    conv_split<<<4096, 256>>>(qkv_w, wqh, wql);
    conv_hw<<<4096, 256>>>(hw_w, whh, whl);
    init_state<<<2048, 256>>>(inputs);

    for (int l = 0; l < 2; l++) {
        const size_t QL = (size_t)l * 2 * 4 * HID * HID;
        const size_t HL = (size_t)l * 2 * 2 * 2 * HID * HID;
        const float* qb = qkv_b + (size_t)l * 2 * 4 * HID;
        const float* hb = hw_b + (size_t)l * 2 * 2 * 2 * HID;

        // QKV: [4096,512] x [1536,512]^T -> fp32 qkv (mode 0)
        gemm_fused<<<dim3(12, 16, 2), 512, GSMEM>>>(
            ahi, alo, wqh + QL, wql + QL, qb, qkvp, nullptr, nullptr,
            nullptr, nullptr, nullptr,
            3 * HID, (size_t)4 * HID * HID, (size_t)4 * HID, (size_t)TOK * 3 * HID, 0, 0);

        attn_kernel<<<dim3(SEQ / 8, BATCH * NHEAD, 2), 256>>>(rel + (size_t)l * 2 * NHEAD * WIN);

        // out projection -> y fp32 + split (mode 1)
        gemm_fused<<<dim3(4, 16, 2), 512, GSMEM>>>(
            athi, atlo, wqh + QL + (size_t)3 * HID * HID, wql + QL + (size_t)3 * HID * HID,
            qb + 3 * HID, yv, yhi, ylo, nullptr, nullptr, nullptr,
            HID, (size_t)4 * HID * HID, (size_t)4 * HID, (size_t)TOK * HID, 1, 0);

        // highway 1 (mode 2)
        gemm_fused<<<dim3(8, 16, 2), 512, GSMEM>>>(
            yhi, ylo, whh + HL, whl + HL, hb, nullptr, y2hi, y2lo,
            yv, nullptr, nullptr,
            2 * HID, (size_t)2 * 2 * HID * HID, (size_t)2 * 2 * HID, 0, 2, 0);

        // highway 2 (mode 3)
        gemm_fused<<<dim3(8, 16, 2), 512, GSMEM>>>(
            y2hi, y2lo, whh + HL + (size_t)2 * HID * HID, whl + HL + (size_t)2 * HID * HID,
            hb + 2 * HID, nullptr, ahi, alo,
            yv, st, out + (size_t)l * TOK * 2 * HID,
            2 * HID, (size_t)2 * 2 * HID * HID, (size_t)2 * 2 * HID, 0, 3, l > 0 ? 1 : 0);
    }
}

// round 6
// speedup vs baseline: 1.2925x; 1.2925x over previous
#include <cuda_runtime.h>
#include <cuda_fp16.h>
#include <cstdint>
#include <cstddef>

#define NHEAD 8
#define HID 512
#define DK 64
#define SEQ 1024
#define BATCH 4
#define TOK 4096
#define WIN 34
#define KDIM 512

#define BK 32
#define TILE_B 8192                    // 128 rows * 64B
#define OFF_BHI 8192
#define OFF_BLO 16384
#define STAGE_B 24576                  // A | Bhi | Blo
#define GSMEM (4 * STAGE_B)            // 98304, 4-stage pipeline

// ---------------- scratch ----------------
__device__ float g_st  [2ull * TOK * HID];
__device__ float g_qkv [2ull * TOK * 3 * HID];
__device__ float g_y   [2ull * TOK * HID];
__device__ __half g_act_h [2ull * TOK * HID];
__device__ __half g_attn_h[2ull * TOK * HID];
__device__ __half g_yh    [2ull * TOK * HID];
__device__ __half g_y2h   [2ull * TOK * HID];
__device__ __half g_wqkv_hi[4194304];
__device__ __half g_wqkv_lo[4194304];
__device__ __half g_whw_hi [4194304];
__device__ __half g_whw_lo [4194304];

// ---------------- helpers ----------------
__device__ __forceinline__ uint32_t s2u(const void* p) {
    uint32_t a;
    asm("{ .reg .u64 t; cvta.to.shared.u64 t, %1; cvt.u32.u64 %0, t; }" : "=r"(a) : "l"(p));
    return a;
}
__device__ __forceinline__ void cpasync16(uint32_t dst, const void* src) {
    asm volatile("cp.async.cg.shared.global [%0], [%1], 16;" :: "r"(dst), "l"(src));
}
__device__ __forceinline__ void ldmx4(uint32_t* d, uint32_t a) {
    asm volatile("ldmatrix.sync.aligned.m8n8.x4.shared.b16 {%0,%1,%2,%3}, [%4];"
        : "=r"(d[0]), "=r"(d[1]), "=r"(d[2]), "=r"(d[3]) : "r"(a));
}
__device__ __forceinline__ void mma16816(float* c, const uint32_t* a, const uint32_t* b) {
    asm volatile("mma.sync.aligned.m16n8k16.row.col.f32.f16.f16.f32 "
        "{%0,%1,%2,%3}, {%4,%5,%6,%7}, {%8,%9}, {%0,%1,%2,%3};"
        : "+f"(c[0]), "+f"(c[1]), "+f"(c[2]), "+f"(c[3])
        : "r"(a[0]), "r"(a[1]), "r"(a[2]), "r"(a[3]), "r"(b[0]), "r"(b[1]));
}
__device__ __forceinline__ uint32_t pack_h2(float x, float y) {
    __half2 t = __floats2half2_rn(x, y);
    return *(uint32_t*)&t;
}

// ---------------- weight conversions: fp32 -> fp16 hi + fp16 lo ----------------
__global__ void conv_split(const float* __restrict__ src,
                           __half* __restrict__ hi, __half* __restrict__ lo)
{
    const size_t i = (size_t)blockIdx.x * blockDim.x + threadIdx.x;
    float4 v = ((const float4*)src)[i];
    float f[4] = {v.x, v.y, v.z, v.w};
    __half h[4], l[4];
#pragma unroll
    for (int k = 0; k < 4; k++) {
        h[k] = __float2half(f[k]);
        l[k] = __float2half(f[k] - __half2float(h[k]));
    }
    *(uint2*)(hi + 4 * i) = *(uint2*)h;
    *(uint2*)(lo + 4 * i) = *(uint2*)l;
}

// highway weights: interleave rows so out col 2j=nonlin_j, 2j+1=gate_j
__global__ void conv_hw(const float* __restrict__ src,
                        __half* __restrict__ hi, __half* __restrict__ lo)
{
    const size_t idx = (size_t)blockIdx.x * blockDim.x + threadIdx.x;
    const size_t m   = idx >> 17;
    const size_t rem = idx & 131071;
    const int    r   = (int)(rem >> 7);
    const size_t c4  = rem & 127;
    const int dr = (r < 512) ? (2 * r) : (2 * (r - 512) + 1);
    float4 v = ((const float4*)src)[idx];
    float f[4] = {v.x, v.y, v.z, v.w};
    __half h[4], l[4];
#pragma unroll
    for (int k = 0; k < 4; k++) {
        h[k] = __float2half(f[k]);
        l[k] = __float2half(f[k] - __half2float(h[k]));
    }
    const size_t dst = (m << 17) + (size_t)dr * 128 + c4;
    *(uint2*)(hi + 4 * dst) = *(uint2*)h;
    *(uint2*)(lo + 4 * dst) = *(uint2*)l;
}

// ---------------- fused HMMA GEMM (fp16 2-pass) ----------------
// CTA 128x128, 256 thr, warp tile 64x32 (2x4 warps), BK=32, 4-stage cp.async.
// C = fp16(A)[M,512] @ (Bhi+Blo)[N,512]^T + bias
// mode 0: C fp32 | mode 1: C fp32 + fp16 Sh | mode 2: highway mid | mode 3: highway final
__global__ __launch_bounds__(256)
void gemm_fused(const __half* __restrict__ A,
                const __half* __restrict__ Bhi, const __half* __restrict__ Blo,
                const float* __restrict__ bias, float* __restrict__ C,
                __half* __restrict__ Sh,
                float* __restrict__ Yv, float* __restrict__ St, float* __restrict__ Out,
                int N, size_t sB, size_t sbias, size_t sC, int mode, int add_res)
{
    extern __shared__ char smem[];
    const uint32_t sbase = s2u(smem);
    const int tid = threadIdx.x, lane = tid & 31, wid = tid >> 5;
    const int wm = wid & 1, wn = wid >> 1;
    const int dir = blockIdx.z;
    const int bm = blockIdx.y * 128, bn = blockIdx.x * 128;
    A += (size_t)dir * TOK * KDIM;
    Bhi += (size_t)dir * sB;  Blo += (size_t)dir * sB;
    bias += (size_t)dir * sbias;

    // cp.async coords: 128 rows, 2x16B per thread per array
    const int r  = tid >> 1;
    const int c0 = (tid & 1) * 2;
    const uint32_t xst = (uint32_t)((r >> 1) & 3);
    const uint32_t sro0 = (uint32_t)r * 64 + (((uint32_t)c0 ^ xst) << 4);
    const uint32_t sro1 = (uint32_t)r * 64 + ((((uint32_t)c0 + 1) ^ xst) << 4);

    // ldmatrix coords
    const int m8 = lane >> 3, l7 = lane & 7;
    const uint32_t xm = (uint32_t)((l7 >> 1) & 3);
    const uint32_t a_base = (uint32_t)(wm * 64 + (m8 & 1) * 8 + l7) * 64;
    const uint32_t b_base = (uint32_t)(wn * 32 + (m8 >> 1) * 8 + l7) * 64;
    const uint32_t a_c = (((uint32_t)(m8 >> 1)) ^ (xm & 1)) << 4;
    const uint32_t b_c = (((uint32_t)(m8 & 1)) ^ (xm & 1)) << 4;
    const uint32_t kof[2] = { (xm & 2) << 4, (2u ^ (xm & 2)) << 4 };

    float acc[4][4][4];
#pragma unroll
    for (int i = 0; i < 4; i++)
#pragma unroll
        for (int j = 0; j < 4; j++)
#pragma unroll
            for (int k = 0; k < 4; k++) acc[i][j][k] = 0.f;

#define LOAD_CHUNK(ch, stg) do {                                                   \
        const uint32_t _sb = sbase + (uint32_t)(stg) * STAGE_B;                    \
        const size_t _ga = (size_t)(bm + r) * KDIM + (ch) * BK + c0 * 8;           \
        cpasync16(_sb + sro0,           A + _ga);                                  \
        cpasync16(_sb + sro1,           A + _ga + 8);                              \
        const size_t _gb = (size_t)(bn + r) * KDIM + (ch) * BK + c0 * 8;           \
        cpasync16(_sb + OFF_BHI + sro0, Bhi + _gb);                                \
        cpasync16(_sb + OFF_BHI + sro1, Bhi + _gb + 8);                            \
        cpasync16(_sb + OFF_BLO + sro0, Blo + _gb);                                \
        cpasync16(_sb + OFF_BLO + sro1, Blo + _gb + 8);                            \
        asm volatile("cp.async.commit_group;" ::: "memory");                       \
    } while (0)

    LOAD_CHUNK(0, 0);
    LOAD_CHUNK(1, 1);
    LOAD_CHUNK(2, 2);

    int stg_c = 0;
    int stg_l = 3;
#pragma unroll 1
    for (int ch = 0; ch < 16; ch++) {
        if (ch < 14)      asm volatile("cp.async.wait_group 2;" ::: "memory");
        else if (ch == 14) asm volatile("cp.async.wait_group 1;" ::: "memory");
        else              asm volatile("cp.async.wait_group 0;" ::: "memory");
        __syncthreads();
        if (ch + 3 < 16) LOAD_CHUNK(ch + 3, stg_l);

        const uint32_t sb = sbase + (uint32_t)stg_c * STAGE_B;
#pragma unroll
        for (int kk = 0; kk < 2; kk++) {
            uint32_t a[4][4], bh[2][4], bl[2][4];
#pragma unroll
            for (int nj = 0; nj < 2; nj++) {
                const uint32_t ba = sb + OFF_BHI + b_base + nj * 1024 + b_c + kof[kk];
                ldmx4(bh[nj], ba);
                ldmx4(bl[nj], ba + (OFF_BLO - OFF_BHI));
            }
#pragma unroll
            for (int mi = 0; mi < 4; mi++)
                ldmx4(a[mi], sb + a_base + mi * 1024 + a_c + kof[kk]);
#pragma unroll
            for (int mi = 0; mi < 4; mi++)
#pragma unroll
                for (int ni = 0; ni < 4; ni++) {
                    const uint32_t* fh = &bh[ni >> 1][(ni & 1) * 2];
                    const uint32_t* fl = &bl[ni >> 1][(ni & 1) * 2];
                    mma16816(acc[mi][ni], a[mi], fh);
                    mma16816(acc[mi][ni], a[mi], fl);
                }
        }
        stg_c = (stg_c + 1) & 3;
        stg_l = (stg_l + 1) & 3;
    }
#undef LOAD_CHUNK

    // ---------------- epilogue ----------------
    const int gr = lane >> 2, gc = (lane & 3) * 2;

    if (mode <= 1) {
        float* Cp = C + (size_t)dir * sC;
        __half* SH = Sh ? (Sh + (size_t)dir * sC) : nullptr;
#pragma unroll
        for (int mi = 0; mi < 4; mi++) {
#pragma unroll
            for (int ni = 0; ni < 4; ni++) {
                const int row0 = bm + wm * 64 + mi * 16 + gr;
                const int col  = bn + wn * 32 + ni * 8 + gc;
                const float b0 = bias[col], b1 = bias[col + 1];
                const float v00 = acc[mi][ni][0] + b0, v01 = acc[mi][ni][1] + b1;
                const float v10 = acc[mi][ni][2] + b0, v11 = acc[mi][ni][3] + b1;
                *(float2*)&Cp[(size_t)row0 * N + col]       = make_float2(v00, v01);
                *(float2*)&Cp[(size_t)(row0 + 8) * N + col] = make_float2(v10, v11);
                if (mode == 1) {
                    *(uint32_t*)&SH[(size_t)row0 * N + col]       = pack_h2(v00, v01);
                    *(uint32_t*)&SH[(size_t)(row0 + 8) * N + col] = pack_h2(v10, v11);
                }
            }
        }
    } else {
        float* Y = Yv + (size_t)dir * TOK * HID;
        float* S = St + (size_t)dir * TOK * HID;
        __half* SH = Sh + (size_t)dir * TOK * HID;
#pragma unroll
        for (int mi = 0; mi < 4; mi++) {
#pragma unroll
            for (int ni = 0; ni < 4; ni++) {
                const int row0 = bm + wm * 64 + mi * 16 + gr;
                const int col  = bn + wn * 32 + ni * 8 + gc;
                const int j    = col >> 1;
                const float bnl = bias[j], bgt = bias[j + HID];
#pragma unroll
                for (int rr = 0; rr < 2; rr++) {
                    const int row = row0 + rr * 8;
                    const float n = acc[mi][ni][rr * 2]     + bnl;
                    const float g = acc[mi][ni][rr * 2 + 1] + bgt;
                    const size_t o = (size_t)row * HID + j;
                    const float yo = Y[o];
                    const float s = 1.f / (1.f + __expf(-g));
                    float v = s * yo + (1.f - s) * fmaxf(n, 0.f);
                    if (mode == 2) {
                        Y[o] = v;
                    } else {
                        if (add_res) v += S[o];
                        S[o] = v;
                        Out[(size_t)row * (2 * HID) + (size_t)dir * HID + j] = v;
                    }
                    SH[o] = __float2half(v);
                }
            }
        }
    }
}

// ---------------- banded local attention ----------------
__global__ void attn_kernel(const float* __restrict__ rel_l)
{
    const int dir = blockIdx.z;
    const int bh = blockIdx.y;
    const int b = bh >> 3;
    const int h = bh & 7;
    const int w = threadIdx.x >> 5;
    const int lane = threadIdx.x & 31;
    const int i = blockIdx.x * 8 + w;

    __shared__ float sbias[WIN];
    if (threadIdx.x < WIN)
        sbias[threadIdx.x] = rel_l[((size_t)dir * NHEAD + h) * WIN + threadIdx.x];
    __syncthreads();

    const size_t dbase = (size_t)dir * TOK * (3 * HID);
    const int tb = b * SEQ;
    const float2 qv = *(const float2*)(g_qkv + dbase + (size_t)(tb + i) * (3 * HID) + h * DK + 2 * lane);

    float m = -1e30f, den = 0.f;
    float2 acc = make_float2(0.f, 0.f);

#pragma unroll 1
    for (int jj = 0; jj < WIN; jj++) {
        const int j = (dir == 0) ? (i - (WIN - 1) + jj) : (i + jj);
        if (j < 0 || j >= SEQ) continue;
        const size_t kbase = dbase + (size_t)(tb + j) * (3 * HID) + h * DK + 2 * lane;
        const float2 kv = *(const float2*)(g_qkv + kbase + HID);
        float p = qv.x * kv.x + qv.y * kv.y;
#pragma unroll
        for (int o = 16; o > 0; o >>= 1) p += __shfl_xor_sync(0xffffffffu, p, o);
        const float s = p * 0.125f + sbias[jj];
        const float mnew = fmaxf(m, s);
        const float sc = __expf(m - mnew);
        const float e  = __expf(s - mnew);
        const float2 vv = *(const float2*)(g_qkv + kbase + 2 * HID);
        den   = den   * sc + e;
        acc.x = acc.x * sc + e * vv.x;
        acc.y = acc.y * sc + e * vv.y;
        m = mnew;
    }
    const float inv = 1.0f / den;
    const size_t oidx = (size_t)dir * TOK * HID + (size_t)(tb + i) * HID + h * DK + 2 * lane;
    *(uint32_t*)&g_attn_h[oidx] = pack_h2(acc.x * inv, acc.y * inv);
}

// ---------------- init: fp16 activation (both dirs) ----------------
__global__ void init_state(const float* __restrict__ in)
{
    const size_t idx = (size_t)blockIdx.x * blockDim.x + threadIdx.x;
    const float4 v = *(const float4*)(in + idx * 4);
    const uint2 p = make_uint2(pack_h2(v.x, v.y), pack_h2(v.z, v.w));
    *(uint2*)&g_act_h[idx * 4] = p;
    *(uint2*)&g_act_h[(size_t)TOK * HID + idx * 4] = p;
}

// ---------------- launch ----------------
extern "C" void kernel_launch(void* const* d_in, const int* in_sizes, int n_in,
                              void* d_out, int out_size)
{
    const float* inputs = (const float*)d_in[0];
    const float* qkv_w  = (const float*)d_in[2];
    const float* qkv_b  = (const float*)d_in[3];
    const float* rel    = (const float*)d_in[4];
    const float* hw_w   = (const float*)d_in[5];
    const float* hw_b   = (const float*)d_in[6];
    float* out = (float*)d_out;

    float *qkvp, *yv, *st;
    __half *ah, *ath, *yh, *y2h, *wqh, *wql, *whh, *whl;
    cudaGetSymbolAddress((void**)&qkvp, g_qkv);
    cudaGetSymbolAddress((void**)&yv,   g_y);
    cudaGetSymbolAddress((void**)&st,   g_st);
    cudaGetSymbolAddress((void**)&ah,   g_act_h);
    cudaGetSymbolAddress((void**)&ath,  g_attn_h);
    cudaGetSymbolAddress((void**)&yh,   g_yh);
    cudaGetSymbolAddress((void**)&y2h,  g_y2h);
    cudaGetSymbolAddress((void**)&wqh,  g_wqkv_hi);
    cudaGetSymbolAddress((void**)&wql,  g_wqkv_lo);
    cudaGetSymbolAddress((void**)&whh,  g_whw_hi);
    cudaGetSymbolAddress((void**)&whl,  g_whw_lo);

    cudaFuncSetAttribute(gemm_fused, cudaFuncAttributeMaxDynamicSharedMemorySize, GSMEM);

    conv_split<<<4096, 256>>>(qkv_w, wqh, wql);
    conv_hw<<<4096, 256>>>(hw_w, whh, whl);
    init_state<<<2048, 256>>>(inputs);

    for (int l = 0; l < 2; l++) {
        const size_t QL = (size_t)l * 2 * 4 * HID * HID;
        const size_t HL = (size_t)l * 2 * 2 * 2 * HID * HID;
        const float* qb = qkv_b + (size_t)l * 2 * 4 * HID;
        const float* hb = hw_b + (size_t)l * 2 * 2 * 2 * HID;

        // QKV: [4096,512] x [1536,512]^T -> fp32 qkv (mode 0)
        gemm_fused<<<dim3(12, 32, 2), 256, GSMEM>>>(
            ah, wqh + QL, wql + QL, qb, qkvp, nullptr,
            nullptr, nullptr, nullptr,
            3 * HID, (size_t)4 * HID * HID, (size_t)4 * HID, (size_t)TOK * 3 * HID, 0, 0);

        attn_kernel<<<dim3(SEQ / 8, BATCH * NHEAD, 2), 256>>>(rel + (size_t)l * 2 * NHEAD * WIN);

        // out projection -> y fp32 + fp16 (mode 1)
        gemm_fused<<<dim3(4, 32, 2), 256, GSMEM>>>(
            ath, wqh + QL + (size_t)3 * HID * HID, wql + QL + (size_t)3 * HID * HID,
            qb + 3 * HID, yv, yh, nullptr, nullptr, nullptr,
            HID, (size_t)4 * HID * HID, (size_t)4 * HID, (size_t)TOK * HID, 1, 0);

        // highway 1 (mode 2): reads yh, updates y fp32, emits y2h
        gemm_fused<<<dim3(8, 32, 2), 256, GSMEM>>>(
            yh, whh + HL, whl + HL, hb, nullptr, y2h,
            yv, nullptr, nullptr,
            2 * HID, (size_t)2 * 2 * HID * HID, (size_t)2 * 2 * HID, 0, 2, 0);

        // highway 2 (mode 3): residual + state + concat + next-layer act
        gemm_fused<<<dim3(8, 32, 2), 256, GSMEM>>>(
            y2h, whh + HL + (size_t)2 * HID * HID, whl + HL + (size_t)2 * HID * HID,
            hb + 2 * HID, nullptr, ah,
            yv, st, out + (size_t)l * TOK * 2 * HID,
            2 * HID, (size_t)2 * 2 * HID * HID, (size_t)2 * 2 * HID, 0, 3, l > 0 ? 1 : 0);
    }
}

// round 7
// speedup vs baseline: 1.6133x; 1.2482x over previous
#include <cuda_runtime.h>
#include <cuda_fp16.h>
#include <cstdint>
#include <cstddef>

#define NHEAD 8
#define HID 512
#define DK 64
#define SEQ 1024
#define BATCH 4
#define TOK 4096
#define WIN 34
#define KDIM 512

#define BK 64
#define TILE_B 16384                   // 128 rows * 128B
#define OFF_B 16384
#define STAGE_B 32768                  // A | B
#define GSMEM (3 * STAGE_B)            // 98304, 3-stage pipeline

// ---------------- scratch ----------------
__device__ float g_st  [2ull * TOK * HID];
__device__ float g_qkv [2ull * TOK * 3 * HID];
__device__ float g_y   [2ull * TOK * HID];
__device__ __half g_act_h [2ull * TOK * HID];
__device__ __half g_attn_h[2ull * TOK * HID];
__device__ __half g_yh    [2ull * TOK * HID];
__device__ __half g_y2h   [2ull * TOK * HID];
__device__ __half g_wqkv  [4194304];
__device__ __half g_whw   [4194304];

// ---------------- helpers ----------------
__device__ __forceinline__ uint32_t s2u(const void* p) {
    uint32_t a;
    asm("{ .reg .u64 t; cvta.to.shared.u64 t, %1; cvt.u32.u64 %0, t; }" : "=r"(a) : "l"(p));
    return a;
}
__device__ __forceinline__ void cpasync16(uint32_t dst, const void* src) {
    asm volatile("cp.async.cg.shared.global [%0], [%1], 16;" :: "r"(dst), "l"(src));
}
__device__ __forceinline__ void ldmx4(uint32_t* d, uint32_t a) {
    asm volatile("ldmatrix.sync.aligned.m8n8.x4.shared.b16 {%0,%1,%2,%3}, [%4];"
        : "=r"(d[0]), "=r"(d[1]), "=r"(d[2]), "=r"(d[3]) : "r"(a));
}
__device__ __forceinline__ void mma16816(float* c, const uint32_t* a, const uint32_t* b) {
    asm volatile("mma.sync.aligned.m16n8k16.row.col.f32.f16.f16.f32 "
        "{%0,%1,%2,%3}, {%4,%5,%6,%7}, {%8,%9}, {%0,%1,%2,%3};"
        : "+f"(c[0]), "+f"(c[1]), "+f"(c[2]), "+f"(c[3])
        : "r"(a[0]), "r"(a[1]), "r"(a[2]), "r"(a[3]), "r"(b[0]), "r"(b[1]));
}
__device__ __forceinline__ uint32_t pack_h2(float x, float y) {
    __half2 t = __floats2half2_rn(x, y);
    return *(uint32_t*)&t;
}

// ---------------- weight conversion: fp32 -> fp16 ----------------
__global__ void conv_w(const float* __restrict__ src, __half* __restrict__ dst)
{
    const size_t i = (size_t)blockIdx.x * blockDim.x + threadIdx.x;
    float4 v = ((const float4*)src)[i];
    *(uint2*)(dst + 4 * i) = make_uint2(pack_h2(v.x, v.y), pack_h2(v.z, v.w));
}

// highway weights: interleave rows so out col 2j=nonlin_j, 2j+1=gate_j
__global__ void conv_hw(const float* __restrict__ src, __half* __restrict__ dst)
{
    const size_t idx = (size_t)blockIdx.x * blockDim.x + threadIdx.x;
    const size_t m   = idx >> 17;
    const size_t rem = idx & 131071;
    const int    r   = (int)(rem >> 7);
    const size_t c4  = rem & 127;
    const int dr = (r < 512) ? (2 * r) : (2 * (r - 512) + 1);
    float4 v = ((const float4*)src)[idx];
    const size_t d = (m << 17) + (size_t)dr * 128 + c4;
    *(uint2*)(dst + 4 * d) = make_uint2(pack_h2(v.x, v.y), pack_h2(v.z, v.w));
}

// ---------------- fused HMMA GEMM (single fp16 pass) ----------------
// CTA 128x128, 256 thr, warp tile 64x32 (2x4 warps), BK=64, 3-stage cp.async.
// C = fp16(A)[M,512] @ fp16(B)[N,512]^T + bias
// mode 0: C fp32 | mode 1: C fp32 + fp16 Sh | mode 2: highway mid | mode 3: highway final
__global__ __launch_bounds__(256, 2)
void gemm_fused(const __half* __restrict__ A, const __half* __restrict__ B,
                const float* __restrict__ bias, float* __restrict__ C,
                __half* __restrict__ Sh,
                float* __restrict__ Yv, float* __restrict__ St, float* __restrict__ Out,
                int N, size_t sB, size_t sbias, size_t sC, int mode, int add_res)
{
    extern __shared__ char smem[];
    const uint32_t sbase = s2u(smem);
    const int tid = threadIdx.x, lane = tid & 31, wid = tid >> 5;
    const int wm = wid & 1, wn = wid >> 1;
    const int dir = blockIdx.z;
    const int bm = blockIdx.y * 128, bn = blockIdx.x * 128;
    A += (size_t)dir * TOK * KDIM;
    B += (size_t)dir * sB;
    bias += (size_t)dir * sbias;

    // cp.async coords: 128 rows x 8 16B-units; 4 units per thread per array
    const int r  = tid >> 1;
    const int c0 = (tid & 1) * 4;
    const uint32_t r7 = (uint32_t)(r & 7);
    uint32_t swz[4];
#pragma unroll
    for (int u = 0; u < 4; u++)
        swz[u] = (uint32_t)r * 128 + ((((uint32_t)(c0 + u)) ^ r7) << 4);

    // ldmatrix coords (SW128: col16 ^= row&7)
    const int m8 = lane >> 3, l7 = lane & 7;
    const uint32_t a_row = (uint32_t)(wm * 64 + (m8 & 1) * 8 + l7) * 128;
    const uint32_t b_row = (uint32_t)(wn * 32 + (m8 >> 1) * 8 + l7) * 128;
    uint32_t acol[4], bcol[4];
#pragma unroll
    for (int kk = 0; kk < 4; kk++) {
        acol[kk] = ((uint32_t)(kk * 2 + (m8 >> 1)) ^ (uint32_t)l7) << 4;
        bcol[kk] = ((uint32_t)(kk * 2 + (m8 & 1)) ^ (uint32_t)l7) << 4;
    }

    float acc[4][4][4];
#pragma unroll
    for (int i = 0; i < 4; i++)
#pragma unroll
        for (int j = 0; j < 4; j++)
#pragma unroll
            for (int k = 0; k < 4; k++) acc[i][j][k] = 0.f;

#define LOAD_CHUNK(ch, stg) do {                                                   \
        const uint32_t _sb = sbase + (uint32_t)(stg) * STAGE_B;                    \
        const size_t _ga = (size_t)(bm + r) * KDIM + (ch) * BK + c0 * 8;           \
        const size_t _gb = (size_t)(bn + r) * KDIM + (ch) * BK + c0 * 8;           \
        cpasync16(_sb + swz[0],         A + _ga);                                  \
        cpasync16(_sb + swz[1],         A + _ga + 8);                              \
        cpasync16(_sb + swz[2],         A + _ga + 16);                             \
        cpasync16(_sb + swz[3],         A + _ga + 24);                             \
        cpasync16(_sb + OFF_B + swz[0], B + _gb);                                  \
        cpasync16(_sb + OFF_B + swz[1], B + _gb + 8);                              \
        cpasync16(_sb + OFF_B + swz[2], B + _gb + 16);                             \
        cpasync16(_sb + OFF_B + swz[3], B + _gb + 24);                             \
        asm volatile("cp.async.commit_group;" ::: "memory");                       \
    } while (0)

    LOAD_CHUNK(0, 0);
    LOAD_CHUNK(1, 1);

    int stg_c = 0;
    int stg_l = 2;
#pragma unroll 1
    for (int ch = 0; ch < 8; ch++) {
        if (ch < 7) asm volatile("cp.async.wait_group 1;" ::: "memory");
        else        asm volatile("cp.async.wait_group 0;" ::: "memory");
        __syncthreads();
        if (ch + 2 < 8) LOAD_CHUNK(ch + 2, stg_l);

        const uint32_t sb = sbase + (uint32_t)stg_c * STAGE_B;
#pragma unroll
        for (int kk = 0; kk < 4; kk++) {
            uint32_t a[4][4], b[2][4];
#pragma unroll
            for (int nj = 0; nj < 2; nj++)
                ldmx4(b[nj], sb + OFF_B + b_row + nj * 2048 + bcol[kk]);
#pragma unroll
            for (int mi = 0; mi < 4; mi++)
                ldmx4(a[mi], sb + a_row + mi * 2048 + acol[kk]);
#pragma unroll
            for (int mi = 0; mi < 4; mi++)
#pragma unroll
                for (int ni = 0; ni < 4; ni++)
                    mma16816(acc[mi][ni], a[mi], &b[ni >> 1][(ni & 1) * 2]);
        }
        stg_c = (stg_c == 2) ? 0 : stg_c + 1;
        stg_l = (stg_l == 2) ? 0 : stg_l + 1;
    }
#undef LOAD_CHUNK

    // ---------------- epilogue ----------------
    const int gr = lane >> 2, gc = (lane & 3) * 2;

    if (mode <= 1) {
        float* Cp = C + (size_t)dir * sC;
        __half* SH = Sh ? (Sh + (size_t)dir * sC) : nullptr;
#pragma unroll
        for (int mi = 0; mi < 4; mi++) {
#pragma unroll
            for (int ni = 0; ni < 4; ni++) {
                const int row0 = bm + wm * 64 + mi * 16 + gr;
                const int col  = bn + wn * 32 + ni * 8 + gc;
                const float b0 = bias[col], b1 = bias[col + 1];
                const float v00 = acc[mi][ni][0] + b0, v01 = acc[mi][ni][1] + b1;
                const float v10 = acc[mi][ni][2] + b0, v11 = acc[mi][ni][3] + b1;
                *(float2*)&Cp[(size_t)row0 * N + col]       = make_float2(v00, v01);
                *(float2*)&Cp[(size_t)(row0 + 8) * N + col] = make_float2(v10, v11);
                if (mode == 1) {
                    *(uint32_t*)&SH[(size_t)row0 * N + col]       = pack_h2(v00, v01);
                    *(uint32_t*)&SH[(size_t)(row0 + 8) * N + col] = pack_h2(v10, v11);
                }
            }
        }
    } else {
        float* Y = Yv + (size_t)dir * TOK * HID;
        float* S = St + (size_t)dir * TOK * HID;
        __half* SH = Sh + (size_t)dir * TOK * HID;
#pragma unroll
        for (int mi = 0; mi < 4; mi++) {
#pragma unroll
            for (int ni = 0; ni < 4; ni++) {
                const int row0 = bm + wm * 64 + mi * 16 + gr;
                const int col  = bn + wn * 32 + ni * 8 + gc;
                const int j    = col >> 1;
                const float bnl = bias[j], bgt = bias[j + HID];
#pragma unroll
                for (int rr = 0; rr < 2; rr++) {
                    const int row = row0 + rr * 8;
                    const float n = acc[mi][ni][rr * 2]     + bnl;
                    const float g = acc[mi][ni][rr * 2 + 1] + bgt;
                    const size_t o = (size_t)row * HID + j;
                    const float yo = Y[o];
                    const float s = 1.f / (1.f + __expf(-g));
                    float v = s * yo + (1.f - s) * fmaxf(n, 0.f);
                    if (mode == 2) {
                        Y[o] = v;
                    } else {
                        if (add_res) v += S[o];
                        S[o] = v;
                        Out[(size_t)row * (2 * HID) + (size_t)dir * HID + j] = v;
                    }
                    SH[o] = __float2half(v);
                }
            }
        }
    }
}

// ---------------- banded local attention ----------------
__global__ void attn_kernel(const float* __restrict__ rel_l)
{
    const int dir = blockIdx.z;
    const int bh = blockIdx.y;
    const int b = bh >> 3;
    const int h = bh & 7;
    const int w = threadIdx.x >> 5;
    const int lane = threadIdx.x & 31;
    const int i = blockIdx.x * 8 + w;

    __shared__ float sbias[WIN];
    if (threadIdx.x < WIN)
        sbias[threadIdx.x] = rel_l[((size_t)dir * NHEAD + h) * WIN + threadIdx.x];
    __syncthreads();

    const size_t dbase = (size_t)dir * TOK * (3 * HID);
    const int tb = b * SEQ;
    const float2 qv = *(const float2*)(g_qkv + dbase + (size_t)(tb + i) * (3 * HID) + h * DK + 2 * lane);

    float m = -1e30f, den = 0.f;
    float2 acc = make_float2(0.f, 0.f);

#pragma unroll 1
    for (int jj = 0; jj < WIN; jj++) {
        const int j = (dir == 0) ? (i - (WIN - 1) + jj) : (i + jj);
        if (j < 0 || j >= SEQ) continue;
        const size_t kbase = dbase + (size_t)(tb + j) * (3 * HID) + h * DK + 2 * lane;
        const float2 kv = *(const float2*)(g_qkv + kbase + HID);
        float p = qv.x * kv.x + qv.y * kv.y;
#pragma unroll
        for (int o = 16; o > 0; o >>= 1) p += __shfl_xor_sync(0xffffffffu, p, o);
        const float s = p * 0.125f + sbias[jj];
        const float mnew = fmaxf(m, s);
        const float sc = __expf(m - mnew);
        const float e  = __expf(s - mnew);
        const float2 vv = *(const float2*)(g_qkv + kbase + 2 * HID);
        den   = den   * sc + e;
        acc.x = acc.x * sc + e * vv.x;
        acc.y = acc.y * sc + e * vv.y;
        m = mnew;
    }
    const float inv = 1.0f / den;
    const size_t oidx = (size_t)dir * TOK * HID + (size_t)(tb + i) * HID + h * DK + 2 * lane;
    *(uint32_t*)&g_attn_h[oidx] = pack_h2(acc.x * inv, acc.y * inv);
}

// ---------------- init: fp16 activation (both dirs) ----------------
__global__ void init_state(const float* __restrict__ in)
{
    const size_t idx = (size_t)blockIdx.x * blockDim.x + threadIdx.x;
    const float4 v = *(const float4*)(in + idx * 4);
    const uint2 p = make_uint2(pack_h2(v.x, v.y), pack_h2(v.z, v.w));
    *(uint2*)&g_act_h[idx * 4] = p;
    *(uint2*)&g_act_h[(size_t)TOK * HID + idx * 4] = p;
}

// ---------------- launch ----------------
extern "C" void kernel_launch(void* const* d_in, const int* in_sizes, int n_in,
                              void* d_out, int out_size)
{
    const float* inputs = (const float*)d_in[0];
    const float* qkv_w  = (const float*)d_in[2];
    const float* qkv_b  = (const float*)d_in[3];
    const float* rel    = (const float*)d_in[4];
    const float* hw_w   = (const float*)d_in[5];
    const float* hw_b   = (const float*)d_in[6];
    float* out = (float*)d_out;

    float *qkvp, *yv, *st;
    __half *ah, *ath, *yh, *y2h, *wq, *wh;
    cudaGetSymbolAddress((void**)&qkvp, g_qkv);
    cudaGetSymbolAddress((void**)&yv,   g_y);
    cudaGetSymbolAddress((void**)&st,   g_st);
    cudaGetSymbolAddress((void**)&ah,   g_act_h);
    cudaGetSymbolAddress((void**)&ath,  g_attn_h);
    cudaGetSymbolAddress((void**)&yh,   g_yh);
    cudaGetSymbolAddress((void**)&y2h,  g_y2h);
    cudaGetSymbolAddress((void**)&wq,   g_wqkv);
    cudaGetSymbolAddress((void**)&wh,   g_whw);

    cudaFuncSetAttribute(gemm_fused, cudaFuncAttributeMaxDynamicSharedMemorySize, GSMEM);

    conv_w<<<4096, 256>>>(qkv_w, wq);
    conv_hw<<<4096, 256>>>(hw_w, wh);
    init_state<<<2048, 256>>>(inputs);

    for (int l = 0; l < 2; l++) {
        const size_t QL = (size_t)l * 2 * 4 * HID * HID;
        const size_t HL = (size_t)l * 2 * 2 * 2 * HID * HID;
        const float* qb = qkv_b + (size_t)l * 2 * 4 * HID;
        const float* hb = hw_b + (size_t)l * 2 * 2 * 2 * HID;

        // QKV: [4096,512] x [1536,512]^T -> fp32 qkv (mode 0)
        gemm_fused<<<dim3(12, 32, 2), 256, GSMEM>>>(
            ah, wq + QL, qb, qkvp, nullptr,
            nullptr, nullptr, nullptr,
            3 * HID, (size_t)4 * HID * HID, (size_t)4 * HID, (size_t)TOK * 3 * HID, 0, 0);

        attn_kernel<<<dim3(SEQ / 8, BATCH * NHEAD, 2), 256>>>(rel + (size_t)l * 2 * NHEAD * WIN);

        // out projection -> y fp32 + fp16 (mode 1)
        gemm_fused<<<dim3(4, 32, 2), 256, GSMEM>>>(
            ath, wq + QL + (size_t)3 * HID * HID,
            qb + 3 * HID, yv, yh, nullptr, nullptr, nullptr,
            HID, (size_t)4 * HID * HID, (size_t)4 * HID, (size_t)TOK * HID, 1, 0);

        // highway 1 (mode 2): reads yh, updates y fp32, emits y2h
        gemm_fused<<<dim3(8, 32, 2), 256, GSMEM>>>(
            yh, wh + HL, hb, nullptr, y2h,
            yv, nullptr, nullptr,
            2 * HID, (size_t)2 * 2 * HID * HID, (size_t)2 * 2 * HID, 0, 2, 0);

        // highway 2 (mode 3): residual + state + concat + next-layer act
        gemm_fused<<<dim3(8, 32, 2), 256, GSMEM>>>(
            y2h, wh + HL + (size_t)2 * HID * HID,
            hb + 2 * HID, nullptr, ah,
            yv, st, out + (size_t)l * TOK * 2 * HID,
            2 * HID, (size_t)2 * 2 * HID * HID, (size_t)2 * 2 * HID, 0, 3, l > 0 ? 1 : 0);
    }
}

// round 8
// speedup vs baseline: 1.6811x; 1.0420x over previous
#include <cuda_runtime.h>
#include <cuda_fp16.h>
#include <cstdint>
#include <cstddef>

#define NHEAD 8
#define HID 512
#define DK 64
#define SEQ 1024
#define BATCH 4
#define TOK 4096
#define WIN 34
#define KDIM 512

#define BK 64
#define OFF_B 16384
#define STAGE_B 32768                  // A | B
#define GSMEM (3 * STAGE_B)            // 98304, 3-stage pipeline
#define NCTA 296

// ---------------- scratch ----------------
__device__ float g_st  [2ull * TOK * HID];
__device__ float g_qkv [2ull * TOK * 3 * HID];
__device__ float g_y   [2ull * TOK * HID];
__device__ __half g_act_h [2ull * TOK * HID];
__device__ __half g_attn_h[2ull * TOK * HID];
__device__ __half g_yh    [2ull * TOK * HID];
__device__ __half g_y2h   [2ull * TOK * HID];
__device__ __half g_wqkv  [4194304];
__device__ __half g_whw   [4194304];

// ---------------- helpers ----------------
__device__ __forceinline__ uint32_t s2u(const void* p) {
    uint32_t a;
    asm("{ .reg .u64 t; cvta.to.shared.u64 t, %1; cvt.u32.u64 %0, t; }" : "=r"(a) : "l"(p));
    return a;
}
__device__ __forceinline__ void cpasync16(uint32_t dst, const void* src) {
    asm volatile("cp.async.cg.shared.global [%0], [%1], 16;" :: "r"(dst), "l"(src));
}
__device__ __forceinline__ void ldmx4(uint32_t* d, uint32_t a) {
    asm volatile("ldmatrix.sync.aligned.m8n8.x4.shared.b16 {%0,%1,%2,%3}, [%4];"
        : "=r"(d[0]), "=r"(d[1]), "=r"(d[2]), "=r"(d[3]) : "r"(a));
}
__device__ __forceinline__ void mma16816(float* c, const uint32_t* a, const uint32_t* b) {
    asm volatile("mma.sync.aligned.m16n8k16.row.col.f32.f16.f16.f32 "
        "{%0,%1,%2,%3}, {%4,%5,%6,%7}, {%8,%9}, {%0,%1,%2,%3};"
        : "+f"(c[0]), "+f"(c[1]), "+f"(c[2]), "+f"(c[3])
        : "r"(a[0]), "r"(a[1]), "r"(a[2]), "r"(a[3]), "r"(b[0]), "r"(b[1]));
}
__device__ __forceinline__ uint32_t pack_h2(float x, float y) {
    __half2 t = __floats2half2_rn(x, y);
    return *(uint32_t*)&t;
}

// ---------------- weight conversion: fp32 -> fp16 ----------------
__global__ void conv_w(const float* __restrict__ src, __half* __restrict__ dst)
{
    const size_t i = (size_t)blockIdx.x * blockDim.x + threadIdx.x;
    float4 v = ((const float4*)src)[i];
    *(uint2*)(dst + 4 * i) = make_uint2(pack_h2(v.x, v.y), pack_h2(v.z, v.w));
}

// highway weights: interleave rows so out col 2j=nonlin_j, 2j+1=gate_j
__global__ void conv_hw(const float* __restrict__ src, __half* __restrict__ dst)
{
    const size_t idx = (size_t)blockIdx.x * blockDim.x + threadIdx.x;
    const size_t m   = idx >> 17;
    const size_t rem = idx & 131071;
    const int    r   = (int)(rem >> 7);
    const size_t c4  = rem & 127;
    const int dr = (r < 512) ? (2 * r) : (2 * (r - 512) + 1);
    float4 v = ((const float4*)src)[idx];
    const size_t d = (m << 17) + (size_t)dr * 128 + c4;
    *(uint2*)(dst + 4 * d) = make_uint2(pack_h2(v.x, v.y), pack_h2(v.z, v.w));
}

// ---------------- persistent fused HMMA GEMM ----------------
// Fixed grid NCTA; CTA loops tiles t = bx + k*grid. t=((bn*32)+bm)*2+dir.
// Continuous cross-tile pipeline: global chunk stream g (8 chunks/tile),
// 3-stage rotation, one barrier per chunk, prefetch g+2.
__global__ __launch_bounds__(256, 2)
void gemm_fused(const __half* __restrict__ A, const __half* __restrict__ B,
                const float* __restrict__ bias, float* __restrict__ C,
                __half* __restrict__ Sh,
                float* __restrict__ Yv, float* __restrict__ St, float* __restrict__ Out,
                int N, size_t sB, size_t sbias, size_t sC, int mode, int add_res,
                int ntiles)
{
    extern __shared__ char smem[];
    const uint32_t sbase = s2u(smem);
    const int tid = threadIdx.x, lane = tid & 31, wid = tid >> 5;
    const int wm = wid & 1, wn = wid >> 1;

    const int bx = (int)blockIdx.x;
    const int nt = (bx < ntiles) ? ((ntiles - 1 - bx) / (int)gridDim.x + 1) : 0;
    if (nt == 0) return;
    const int total = nt * 8;

    // cp.async coords: 128 rows x 8 16B-units; 4 units per thread per array
    const int r  = tid >> 1;
    const int c0 = (tid & 1) * 4;
    const uint32_t r7 = (uint32_t)(r & 7);
    uint32_t swz[4];
#pragma unroll
    for (int u = 0; u < 4; u++)
        swz[u] = (uint32_t)r * 128 + ((((uint32_t)(c0 + u)) ^ r7) << 4);

    // ldmatrix coords (SW128: col16 ^= row&7)
    const int m8 = lane >> 3, l7 = lane & 7;
    const uint32_t a_row = (uint32_t)(wm * 64 + (m8 & 1) * 8 + l7) * 128;
    const uint32_t b_row = (uint32_t)(wn * 32 + (m8 >> 1) * 8 + l7) * 128;
    uint32_t acol[4], bcol[4];
#pragma unroll
    for (int kk = 0; kk < 4; kk++) {
        acol[kk] = ((uint32_t)(kk * 2 + (m8 >> 1)) ^ (uint32_t)l7) << 4;
        bcol[kk] = ((uint32_t)(kk * 2 + (m8 & 1)) ^ (uint32_t)l7) << 4;
    }

    float acc[4][4][4];
#pragma unroll
    for (int i = 0; i < 4; i++)
#pragma unroll
        for (int j = 0; j < 4; j++)
#pragma unroll
            for (int k = 0; k < 4; k++) acc[i][j][k] = 0.f;

#define LOAD_G(g) do {                                                             \
        const int _t = bx + ((g) >> 3) * (int)gridDim.x;                           \
        const int _dir = _t & 1, _u = _t >> 1;                                     \
        const int _bm = (_u & 31) * 128, _bn = (_u >> 5) * 128;                    \
        const int _ke = ((g) & 7) * BK + c0 * 8;                                   \
        const __half* _Ap = A + (size_t)_dir * (TOK * KDIM)                        \
                              + (size_t)(_bm + r) * KDIM + _ke;                    \
        const __half* _Bp = B + (size_t)_dir * sB + (size_t)(_bn + r) * KDIM + _ke;\
        const uint32_t _sb = sbase + (uint32_t)((g) % 3) * STAGE_B;                \
        cpasync16(_sb + swz[0],         _Ap);                                      \
        cpasync16(_sb + swz[1],         _Ap + 8);                                  \
        cpasync16(_sb + swz[2],         _Ap + 16);                                 \
        cpasync16(_sb + swz[3],         _Ap + 24);                                 \
        cpasync16(_sb + OFF_B + swz[0], _Bp);                                      \
        cpasync16(_sb + OFF_B + swz[1], _Bp + 8);                                  \
        cpasync16(_sb + OFF_B + swz[2], _Bp + 16);                                 \
        cpasync16(_sb + OFF_B + swz[3], _Bp + 24);                                 \
        asm volatile("cp.async.commit_group;" ::: "memory");                       \
    } while (0)

    LOAD_G(0);
    LOAD_G(1);

    const int gr = lane >> 2, gc = (lane & 3) * 2;

#pragma unroll 1
    for (int g = 0; g < total; g++) {
        if (g < total - 1) asm volatile("cp.async.wait_group 1;" ::: "memory");
        else               asm volatile("cp.async.wait_group 0;" ::: "memory");
        __syncthreads();
        if (g + 2 < total) LOAD_G(g + 2);

        const uint32_t sb = sbase + (uint32_t)(g % 3) * STAGE_B;
#pragma unroll
        for (int kk = 0; kk < 4; kk++) {
            uint32_t a[4][4], b[2][4];
#pragma unroll
            for (int nj = 0; nj < 2; nj++)
                ldmx4(b[nj], sb + OFF_B + b_row + nj * 2048 + bcol[kk]);
#pragma unroll
            for (int mi = 0; mi < 4; mi++)
                ldmx4(a[mi], sb + a_row + mi * 2048 + acol[kk]);
#pragma unroll
            for (int mi = 0; mi < 4; mi++)
#pragma unroll
                for (int ni = 0; ni < 4; ni++)
                    mma16816(acc[mi][ni], a[mi], &b[ni >> 1][(ni & 1) * 2]);
        }

        if ((g & 7) == 7) {
            // ---------------- epilogue for finished tile ----------------
            const int t = bx + (g >> 3) * (int)gridDim.x;
            const int dir = t & 1, u = t >> 1;
            const int bm = (u & 31) * 128, bn = (u >> 5) * 128;
            const float* bs = bias + (size_t)dir * sbias;

            if (mode <= 1) {
                float* Cp = C + (size_t)dir * sC;
                __half* SH = Sh ? (Sh + (size_t)dir * sC) : nullptr;
#pragma unroll
                for (int mi = 0; mi < 4; mi++) {
#pragma unroll
                    for (int ni = 0; ni < 4; ni++) {
                        const int row0 = bm + wm * 64 + mi * 16 + gr;
                        const int col  = bn + wn * 32 + ni * 8 + gc;
                        const float b0 = bs[col], b1 = bs[col + 1];
                        const float v00 = acc[mi][ni][0] + b0, v01 = acc[mi][ni][1] + b1;
                        const float v10 = acc[mi][ni][2] + b0, v11 = acc[mi][ni][3] + b1;
                        *(float2*)&Cp[(size_t)row0 * N + col]       = make_float2(v00, v01);
                        *(float2*)&Cp[(size_t)(row0 + 8) * N + col] = make_float2(v10, v11);
                        if (mode == 1) {
                            *(uint32_t*)&SH[(size_t)row0 * N + col]       = pack_h2(v00, v01);
                            *(uint32_t*)&SH[(size_t)(row0 + 8) * N + col] = pack_h2(v10, v11);
                        }
                    }
                }
            } else {
                float* Y = Yv + (size_t)dir * TOK * HID;
                float* S = St ? (St + (size_t)dir * TOK * HID) : nullptr;
                __half* SH = Sh + (size_t)dir * TOK * HID;
#pragma unroll
                for (int mi = 0; mi < 4; mi++) {
#pragma unroll
                    for (int ni = 0; ni < 4; ni++) {
                        const int row0 = bm + wm * 64 + mi * 16 + gr;
                        const int col  = bn + wn * 32 + ni * 8 + gc;
                        const int j    = col >> 1;
                        const float bnl = bs[j], bgt = bs[j + HID];
#pragma unroll
                        for (int rr = 0; rr < 2; rr++) {
                            const int row = row0 + rr * 8;
                            const float n = acc[mi][ni][rr * 2]     + bnl;
                            const float gg = acc[mi][ni][rr * 2 + 1] + bgt;
                            const size_t o = (size_t)row * HID + j;
                            const float yo = Y[o];
                            const float s = 1.f / (1.f + __expf(-gg));
                            float v = s * yo + (1.f - s) * fmaxf(n, 0.f);
                            if (mode == 2) {
                                Y[o] = v;
                            } else {
                                if (add_res) v += S[o];
                                S[o] = v;
                                Out[(size_t)row * (2 * HID) + (size_t)dir * HID + j] = v;
                            }
                            SH[o] = __float2half(v);
                        }
                    }
                }
            }
#pragma unroll
            for (int i = 0; i < 4; i++)
#pragma unroll
                for (int j = 0; j < 4; j++)
#pragma unroll
                    for (int k = 0; k < 4; k++) acc[i][j][k] = 0.f;
        }
    }
#undef LOAD_G
}

// ---------------- banded local attention v2 (smem window, parallel scores) ----
// block: 256 thr / 8 warps; QBLK=64 queries of one (b,h,dir); warp = 8 queries.
// smem floats: Ks[64][100] (transposed K), Vs[97][68], qs[64][68], pb[8][34], sbias[34]
#define ATT_SMEM (17664 * 4)
__global__ void attn_v2(const float* __restrict__ rel_l)
{
    extern __shared__ float sm[];
    float* Ks = sm;               // [64][100]
    float* Vs = sm + 6400;        // [97][68]
    float* qs = sm + 12996;       // [64][68]
    float* pb = sm + 17348;       // [8][34]
    float* sbias = sm + 17620;    // [34]

    const int dir = blockIdx.z;
    const int bh = blockIdx.y;
    const int b = bh >> 3, h = bh & 7;
    const int q0 = blockIdx.x * 64;
    const int tid = threadIdx.x, w = tid >> 5, lane = tid & 31;
    const int W0 = (dir == 0) ? (q0 - 33) : q0;

    const float* base = g_qkv + (size_t)dir * TOK * (3 * HID)
                              + (size_t)(b * SEQ) * (3 * HID) + h * DK;

    if (tid < WIN)
        sbias[tid] = rel_l[((size_t)dir * NHEAD + h) * WIN + tid];

    // load q tile
    for (int idx = tid; idx < 64 * 16; idx += 256) {
        const int row = idx >> 4, dq = (idx & 15) * 4;
        const float4 v = *(const float4*)(base + (size_t)(q0 + row) * 1536 + dq);
        float* qp = qs + row * 68 + dq;
        qp[0] = v.x; qp[1] = v.y; qp[2] = v.z; qp[3] = v.w;
    }
    // load K (transposed) and V window
    for (int idx = tid; idx < 97 * 16; idx += 256) {
        const int jl = idx >> 4, dq = (idx & 15) * 4;
        const int j = W0 + jl;
        float4 kv = make_float4(0.f, 0.f, 0.f, 0.f);
        float4 vv = make_float4(0.f, 0.f, 0.f, 0.f);
        if (j >= 0 && j < SEQ) {
            kv = *(const float4*)(base + HID + (size_t)j * 1536 + dq);
            vv = *(const float4*)(base + 2 * HID + (size_t)j * 1536 + dq);
        }
        Ks[(dq + 0) * 100 + jl] = kv.x;
        Ks[(dq + 1) * 100 + jl] = kv.y;
        Ks[(dq + 2) * 100 + jl] = kv.z;
        Ks[(dq + 3) * 100 + jl] = kv.w;
        float* vp = Vs + jl * 68 + dq;
        vp[0] = vv.x; vp[1] = vv.y; vp[2] = vv.z; vp[3] = vv.w;
    }
    __syncthreads();

#pragma unroll 1
    for (int qq = 0; qq < 8; qq++) {
        const int il = w * 8 + qq;
        const int i = q0 + il;
        const int jj0 = 2 * lane, jj1 = 2 * lane + 1;
        bool v0, v1;
        if (dir == 0) {
            v0 = (jj0 <= 33) && (i - 33 + jj0 >= 0);
            v1 = (jj1 <= 33) && (i - 33 + jj1 >= 0);
        } else {
            v0 = (jj0 <= 33) && (i + jj0 < SEQ);
            v1 = (jj1 <= 33) && (i + jj1 < SEQ);
        }
        const int jl0 = min(il + jj0, 96), jl1 = min(il + jj1, 96);
        float s0 = 0.f, s1 = 0.f;
        const float* qr = qs + il * 68;
#pragma unroll 8
        for (int d = 0; d < 64; d++) {
            const float qd = qr[d];
            s0 += qd * Ks[d * 100 + jl0];
            s1 += qd * Ks[d * 100 + jl1];
        }
        s0 = v0 ? (s0 * 0.125f + sbias[jj0]) : -1e30f;
        s1 = v1 ? (s1 * 0.125f + sbias[jj1]) : -1e30f;
        float m = fmaxf(s0, s1);
#pragma unroll
        for (int o = 16; o > 0; o >>= 1) m = fmaxf(m, __shfl_xor_sync(0xffffffffu, m, o));
        const float e0 = __expf(s0 - m), e1 = __expf(s1 - m);
        float den = e0 + e1;
#pragma unroll
        for (int o = 16; o > 0; o >>= 1) den += __shfl_xor_sync(0xffffffffu, den, o);
        if (lane <= 16) {
            pb[w * 34 + jj0] = e0;
            if (jj1 < 34) pb[w * 34 + jj1] = e1;
        }
        __syncwarp();
        float o0 = 0.f, o1 = 0.f;
#pragma unroll 2
        for (int jj = 0; jj < WIN; jj++) {
            const float p = pb[w * 34 + jj];
            const float2 vv = *(const float2*)&Vs[(il + jj) * 68 + 2 * lane];
            o0 += p * vv.x;
            o1 += p * vv.y;
        }
        const float inv = 1.f / den;
        const size_t oi = (size_t)dir * TOK * HID + (size_t)(b * SEQ + i) * HID + h * DK + 2 * lane;
        *(uint32_t*)&g_attn_h[oi] = pack_h2(o0 * inv, o1 * inv);
        __syncwarp();
    }
}

// ---------------- init: fp16 activation (both dirs) ----------------
__global__ void init_state(const float* __restrict__ in)
{
    const size_t idx = (size_t)blockIdx.x * blockDim.x + threadIdx.x;
    const float4 v = *(const float4*)(in + idx * 4);
    const uint2 p = make_uint2(pack_h2(v.x, v.y), pack_h2(v.z, v.w));
    *(uint2*)&g_act_h[idx * 4] = p;
    *(uint2*)&g_act_h[(size_t)TOK * HID + idx * 4] = p;
}

// ---------------- launch ----------------
extern "C" void kernel_launch(void* const* d_in, const int* in_sizes, int n_in,
                              void* d_out, int out_size)
{
    const float* inputs = (const float*)d_in[0];
    const float* qkv_w  = (const float*)d_in[2];
    const float* qkv_b  = (const float*)d_in[3];
    const float* rel    = (const float*)d_in[4];
    const float* hw_w   = (const float*)d_in[5];
    const float* hw_b   = (const float*)d_in[6];
    float* out = (float*)d_out;

    float *qkvp, *yv, *st;
    __half *ah, *ath, *yh, *y2h, *wq, *wh;
    cudaGetSymbolAddress((void**)&qkvp, g_qkv);
    cudaGetSymbolAddress((void**)&yv,   g_y);
    cudaGetSymbolAddress((void**)&st,   g_st);
    cudaGetSymbolAddress((void**)&ah,   g_act_h);
    cudaGetSymbolAddress((void**)&ath,  g_attn_h);
    cudaGetSymbolAddress((void**)&yh,   g_yh);
    cudaGetSymbolAddress((void**)&y2h,  g_y2h);
    cudaGetSymbolAddress((void**)&wq,   g_wqkv);
    cudaGetSymbolAddress((void**)&wh,   g_whw);

    cudaFuncSetAttribute(gemm_fused, cudaFuncAttributeMaxDynamicSharedMemorySize, GSMEM);
    cudaFuncSetAttribute(attn_v2, cudaFuncAttributeMaxDynamicSharedMemorySize, ATT_SMEM);

    conv_w<<<4096, 256>>>(qkv_w, wq);
    conv_hw<<<4096, 256>>>(hw_w, wh);
    init_state<<<2048, 256>>>(inputs);

    for (int l = 0; l < 2; l++) {
        const size_t QL = (size_t)l * 2 * 4 * HID * HID;
        const size_t HL = (size_t)l * 2 * 2 * 2 * HID * HID;
        const float* qb = qkv_b + (size_t)l * 2 * 4 * HID;
        const float* hb = hw_b + (size_t)l * 2 * 2 * 2 * HID;

        // QKV: 12 bn-tiles * 32 bm-tiles * 2 dirs = 768 tiles (mode 0)
        gemm_fused<<<NCTA, 256, GSMEM>>>(
            ah, wq + QL, qb, qkvp, nullptr,
            nullptr, nullptr, nullptr,
            3 * HID, (size_t)4 * HID * HID, (size_t)4 * HID, (size_t)TOK * 3 * HID, 0, 0, 768);

        attn_v2<<<dim3(SEQ / 64, BATCH * NHEAD, 2), 256, ATT_SMEM>>>(
            rel + (size_t)l * 2 * NHEAD * WIN);

        // out projection: 4 bn-tiles -> 256 tiles (mode 1)
        gemm_fused<<<NCTA, 256, GSMEM>>>(
            ath, wq + QL + (size_t)3 * HID * HID,
            qb + 3 * HID, yv, yh, nullptr, nullptr, nullptr,
            HID, (size_t)4 * HID * HID, (size_t)4 * HID, (size_t)TOK * HID, 1, 0, 256);

        // highway 1: 8 bn-tiles -> 512 tiles (mode 2)
        gemm_fused<<<NCTA, 256, GSMEM>>>(
            yh, wh + HL, hb, nullptr, y2h,
            yv, nullptr, nullptr,
            2 * HID, (size_t)2 * 2 * HID * HID, (size_t)2 * 2 * HID, 0, 2, 0, 512);

        // highway 2: residual + state + concat + next-layer act (mode 3)
        gemm_fused<<<NCTA, 256, GSMEM>>>(
            y2h, wh + HL + (size_t)2 * HID * HID,
            hb + 2 * HID, nullptr, ah,
            yv, st, out + (size_t)l * TOK * 2 * HID,
            2 * HID, (size_t)2 * 2 * HID * HID, (size_t)2 * 2 * HID, 0, 3, l > 0 ? 1 : 0, 512);
    }
}